// round 9
// baseline (speedup 1.0000x reference)
#include <cuda_runtime.h>
#include <cuda_bf16.h>

#define HIDDEN 4096
#define TOKENS 16384
#define TP 4
#define EPS 1e-6f

#define THREADS 512
#define V4_PER_ROW (HIDDEN / 4)              // 1024 float4 per row
#define V4_PER_THREAD (V4_PER_ROW / THREADS) // 2
#define NWARPS (THREADS / 32)                // 16

__global__ __launch_bounds__(THREADS)
void allreduce_rmsnorm_kernel(const float4* __restrict__ hs,
                              const float4* __restrict__ w,
                              float4* __restrict__ out) {
    const int token = blockIdx.x;
    const size_t row = (size_t)token * V4_PER_ROW;
    const size_t tp_stride = (size_t)TOKENS * V4_PER_ROW;

    // Issue all 8 loads j-fastest (consecutive LDGs differ by 2KB -> land in
    // different L2 slices; tp stride = 256MiB = bit28 is OUTSIDE the LTS hash,
    // so t-consecutive issue order would hotspot one slice-pair).
    float4 r[TP][V4_PER_THREAD];
    #pragma unroll
    for (int t = 0; t < TP; t++) {
        #pragma unroll
        for (int j = 0; j < V4_PER_THREAD; j++) {
            const int col = threadIdx.x + j * THREADS;
            r[t][j] = hs[(size_t)t * tp_stride + row + col];
        }
    }

    float4 acc[V4_PER_THREAD];
    float ss = 0.0f;
    #pragma unroll
    for (int j = 0; j < V4_PER_THREAD; j++) {
        float4 v = r[0][j];
        #pragma unroll
        for (int t = 1; t < TP; t++) {
            v.x += r[t][j].x; v.y += r[t][j].y;
            v.z += r[t][j].z; v.w += r[t][j].w;
        }
        acc[j] = v;
        ss += v.x * v.x + v.y * v.y + v.z * v.z + v.w * v.w;
    }

    // Warp-level reduction of sum-of-squares.
    #pragma unroll
    for (int off = 16; off > 0; off >>= 1)
        ss += __shfl_xor_sync(0xFFFFFFFFu, ss, off);

    // Single-barrier block reduction; lanes 16..31 mirror lanes 0..15.
    __shared__ float warp_ss[NWARPS];
    const int lane = threadIdx.x & 31;
    const int wid  = threadIdx.x >> 5;
    if (lane == 0) warp_ss[wid] = ss;
    __syncthreads();

    float s = warp_ss[lane & (NWARPS - 1)];
    #pragma unroll
    for (int off = NWARPS / 2; off > 0; off >>= 1)
        s += __shfl_xor_sync(0xFFFFFFFFu, s, off);
    const float inv_rms = rsqrtf(s * (1.0f / (float)HIDDEN) + EPS);

    #pragma unroll
    for (int j = 0; j < V4_PER_THREAD; j++) {
        const int col = threadIdx.x + j * THREADS;
        const float4 g = __ldg(&w[col]);
        float4 v = acc[j];
        v.x = v.x * inv_rms * g.x;
        v.y = v.y * inv_rms * g.y;
        v.z = v.z * inv_rms * g.z;
        v.w = v.w * inv_rms * g.w;
        out[row + col] = v;
    }
}

extern "C" void kernel_launch(void* const* d_in, const int* in_sizes, int n_in,
                              void* d_out, int out_size) {
    const float4* hs = (const float4*)d_in[0];  // [tp, tokens, hidden] fp32
    // d_in[1] = residual -- unused by the reference computation
    const float4* w  = (const float4*)d_in[2];  // [hidden] fp32
    float4* out = (float4*)d_out;               // [tokens, hidden] fp32

    allreduce_rmsnorm_kernel<<<TOKENS, THREADS>>>(hs, w, out);
}

// round 10
// speedup vs baseline: 1.0008x; 1.0008x over previous
#include <cuda_runtime.h>
#include <cuda_bf16.h>

#define HIDDEN 4096
#define TOKENS 16384
#define TP 4
#define EPS 1e-6f

#define THREADS 512
#define V4_PER_ROW (HIDDEN / 4)              // 1024 float4 per row
#define V4_PER_THREAD (V4_PER_ROW / THREADS) // 2
#define NWARPS (THREADS / 32)                // 16

__global__ __launch_bounds__(THREADS)
void allreduce_rmsnorm_kernel(const float4* __restrict__ hs,
                              const float4* __restrict__ w,
                              float4* __restrict__ out) {
    const int token = blockIdx.x;
    const size_t row = (size_t)token * V4_PER_ROW;
    const size_t tp_stride = (size_t)TOKENS * V4_PER_ROW;

    float4 acc[V4_PER_THREAD];
    float ss = 0.0f;

    // Load + tp-reduce. 8 independent streaming loads per thread.
    #pragma unroll
    for (int j = 0; j < V4_PER_THREAD; j++) {
        const int col = threadIdx.x + j * THREADS;
        float4 v = __ldcs(&hs[row + col]);
        #pragma unroll
        for (int t = 1; t < TP; t++) {
            const float4 u = __ldcs(&hs[(size_t)t * tp_stride + row + col]);
            v.x += u.x; v.y += u.y; v.z += u.z; v.w += u.w;
        }
        acc[j] = v;
        ss += v.x * v.x + v.y * v.y + v.z * v.z + v.w * v.w;
    }

    // Block reduction of sum-of-squares: warp shuffle then shared.
    #pragma unroll
    for (int off = 16; off > 0; off >>= 1)
        ss += __shfl_xor_sync(0xFFFFFFFFu, ss, off);

    __shared__ float warp_ss[NWARPS];
    __shared__ float inv_rms_sh;
    const int lane = threadIdx.x & 31;
    const int wid  = threadIdx.x >> 5;
    if (lane == 0) warp_ss[wid] = ss;
    __syncthreads();

    if (wid == 0) {
        float s = (lane < NWARPS) ? warp_ss[lane] : 0.0f;
        #pragma unroll
        for (int off = NWARPS / 2; off > 0; off >>= 1)
            s += __shfl_xor_sync(0xFFFFFFFFu, s, off);
        if (lane == 0)
            inv_rms_sh = rsqrtf(s * (1.0f / (float)HIDDEN) + EPS);
    }
    __syncthreads();
    const float inv_rms = inv_rms_sh;

    #pragma unroll
    for (int j = 0; j < V4_PER_THREAD; j++) {
        const int col = threadIdx.x + j * THREADS;
        const float4 g = __ldg(&w[col]);
        float4 v = acc[j];
        v.x = v.x * inv_rms * g.x;
        v.y = v.y * inv_rms * g.y;
        v.z = v.z * inv_rms * g.z;
        v.w = v.w * inv_rms * g.w;
        __stcs(&out[row + col], v);
    }
}

extern "C" void kernel_launch(void* const* d_in, const int* in_sizes, int n_in,
                              void* d_out, int out_size) {
    const float4* hs = (const float4*)d_in[0];  // [tp, tokens, hidden] fp32
    // d_in[1] = residual -- unused by the reference computation
    const float4* w  = (const float4*)d_in[2];  // [hidden] fp32
    float4* out = (float4*)d_out;               // [tokens, hidden] fp32

    allreduce_rmsnorm_kernel<<<TOKENS, THREADS>>>(hs, w, out);
}

// round 11
// speedup vs baseline: 1.0081x; 1.0073x over previous
#include <cuda_runtime.h>
#include <cuda_bf16.h>

#define HIDDEN 4096
#define TOKENS 16384
#define TP 4
#define EPS 1e-6f

#define THREADS 512
#define V4_PER_ROW (HIDDEN / 4)              // 1024 float4 per row
#define V4_PER_THREAD (V4_PER_ROW / THREADS) // 2
#define NWARPS (THREADS / 32)                // 16

__global__ __launch_bounds__(THREADS)
void allreduce_rmsnorm_kernel(const float4* __restrict__ hs,
                              const float4* __restrict__ w,
                              float4* __restrict__ out) {
    const int token = blockIdx.x;
    const size_t row = (size_t)token * V4_PER_ROW;
    const size_t tp_stride = (size_t)TOKENS * V4_PER_ROW;

    float4 acc[V4_PER_THREAD];
    float ss = 0.0f;

    // Load + tp-reduce. 8 independent fully-coalesced loads per thread.
    #pragma unroll
    for (int j = 0; j < V4_PER_THREAD; j++) {
        const int col = threadIdx.x + j * THREADS;
        float4 v = hs[row + col];
        #pragma unroll
        for (int t = 1; t < TP; t++) {
            const float4 u = hs[(size_t)t * tp_stride + row + col];
            v.x += u.x; v.y += u.y; v.z += u.z; v.w += u.w;
        }
        acc[j] = v;
        ss += v.x * v.x + v.y * v.y + v.z * v.z + v.w * v.w;
    }

    // Warp-level reduction of sum-of-squares.
    #pragma unroll
    for (int off = 16; off > 0; off >>= 1)
        ss += __shfl_xor_sync(0xFFFFFFFFu, ss, off);

    // Single-barrier block reduction: each warp publishes its partial, then
    // EVERY warp reduces all 16 partials itself (no 2nd barrier, no broadcast
    // dependency on warp 0). Lanes 16..31 mirror lanes 0..15 so the
    // {8,4,2,1} butterfly (which never crosses the lane-16 boundary) yields
    // the full block sum in every lane.
    __shared__ float warp_ss[NWARPS];
    const int lane = threadIdx.x & 31;
    const int wid  = threadIdx.x >> 5;
    if (lane == 0) warp_ss[wid] = ss;
    __syncthreads();

    float s = warp_ss[lane & (NWARPS - 1)];
    #pragma unroll
    for (int off = NWARPS / 2; off > 0; off >>= 1)
        s += __shfl_xor_sync(0xFFFFFFFFu, s, off);
    const float inv_rms = rsqrtf(s * (1.0f / (float)HIDDEN) + EPS);

    #pragma unroll
    for (int j = 0; j < V4_PER_THREAD; j++) {
        const int col = threadIdx.x + j * THREADS;
        const float4 g = __ldg(&w[col]);
        float4 v = acc[j];
        v.x = v.x * inv_rms * g.x;
        v.y = v.y * inv_rms * g.y;
        v.z = v.z * inv_rms * g.z;
        v.w = v.w * inv_rms * g.w;
        out[row + col] = v;
    }
}

extern "C" void kernel_launch(void* const* d_in, const int* in_sizes, int n_in,
                              void* d_out, int out_size) {
    const float4* hs = (const float4*)d_in[0];  // [tp, tokens, hidden] fp32
    // d_in[1] = residual -- unused by the reference computation
    const float4* w  = (const float4*)d_in[2];  // [hidden] fp32
    float4* out = (float4*)d_out;               // [tokens, hidden] fp32

    allreduce_rmsnorm_kernel<<<TOKENS, THREADS>>>(hs, w, out);
}